// round 10
// baseline (speedup 1.0000x reference)
#include <cuda_runtime.h>
#include <stdint.h>

constexpr int S_DIM = 16384;
constexpr int T_DIM = 8192;
constexpr int B_DIM = 16;
constexpr int NH    = 16;
constexpr int KEEP  = 24;
constexpr int CAP   = 128;
constexpr int TRIG  = 96;
constexpr unsigned FULLM = 0xFFFFFFFFu;

constexpr size_t OFF_XNEAR = 0;
constexpr size_t OFF_IDIST = (size_t)B_DIM * T_DIM * NH;      // 2097152
constexpr size_t OFF_ILON  = OFF_IDIST + (size_t)T_DIM * NH;  // 2228224
constexpr size_t OFF_ILAT  = OFF_ILON  + (size_t)T_DIM * NH;  // 2359296

__device__ __forceinline__ unsigned saddr(const void* p) {
    return (unsigned)__cvta_generic_to_shared(p);
}
#define CP16(dst_s, src_g) \
    asm volatile("cp.async.cg.shared.global [%0], [%1], 16;" :: "r"(dst_s), "l"(src_g))
#define CPCOMMIT() asm volatile("cp.async.commit_group;" ::: "memory")
#define CPWAIT2()  asm volatile("cp.async.wait_group 2;"  ::: "memory")

// Pack (nonneg float, index): unsigned order == (value asc, index asc),
// exactly jax.lax.top_k's stable order.
__device__ __forceinline__ unsigned long long pack_key(float v, unsigned idx) {
    return ((unsigned long long)__float_as_uint(v) << 32) | idx;
}

__device__ __forceinline__ unsigned long long warp_min64(unsigned long long v) {
    #pragma unroll
    for (int o = 16; o > 0; o >>= 1) {
        unsigned long long w = __shfl_xor_sync(FULLM, v, o);
        if (w < v) v = w;
    }
    return v;
}

// Warp-collective: write `rounds` smallest keys of buf[0..cnt) sorted into
// buf[0..rounds); returns the rounds-th smallest. Keys unique (distinct idx).
__device__ __forceinline__ unsigned long long select_sorted(
    unsigned long long* buf, int cnt, int rounds, int lane)
{
    unsigned long long k[CAP / 32];
    unsigned long long lmin = ~0ull;
    #pragma unroll
    for (int q = 0; q < CAP / 32; q++) {
        int p = lane + 32 * q;
        k[q] = (p < cnt) ? buf[p] : ~0ull;
        if (k[q] < lmin) lmin = k[q];
    }
    unsigned long long g = ~0ull;
    for (int r = 0; r < rounds; r++) {
        g = warp_min64(lmin);
        if (lmin == g) {
            unsigned long long nl = ~0ull;
            #pragma unroll
            for (int q = 0; q < CAP / 32; q++) {
                if (k[q] == g) k[q] = ~0ull;
                if (k[q] < nl) nl = k[q];
            }
            lmin = nl;
        }
        if (lane == 0) buf[r] = g;
    }
    __syncwarp();
    return g;
}

// Append passing lanes; rebuild keeps KEEP best and tightens thr (inclusive).
__device__ __forceinline__ void try_append(bool p, float v, unsigned idx,
    unsigned long long* buf, int& cnt, float& thr, int lane)
{
    unsigned m = __ballot_sync(FULLM, p);
    if (m == 0) return;
    if (p) buf[cnt + __popc(m & ((1u << lane) - 1u))] = pack_key(v, idx);
    cnt += __popc(m);
    if (cnt > TRIG) {
        __syncwarp();
        unsigned long long g = select_sorted(buf, cnt, KEEP, lane);
        cnt = KEEP;
        thr = __uint_as_float((unsigned)(g >> 32));
    }
}

__device__ __forceinline__ void filt4(float s0, float s1, float s2, float s3,
    unsigned base, unsigned long long* buf, int& cnt, float& thr, int lane)
{
    try_append(s0 <= thr, s0, base + 0u, buf, cnt, thr, lane);
    try_append(s1 <= thr, s1, base + 1u, buf, cnt, thr, lane);
    try_append(s2 <= thr, s2, base + 2u, buf, cnt, thr, lane);
    try_append(s3 <= thr, s3, base + 3u, buf, cnt, thr, lane);
}

__global__ __launch_bounds__(128)
void nn_topk_kernel(const float* __restrict__ x,
                    const float* __restrict__ dlon,
                    const float* __restrict__ dlat,
                    float* __restrict__ out)
{
    // Uniform rings: 4 warps x 4 slots x 128 float4 (2KB/slot).
    // Dist warps (0,1): slot = [0..63]=dlon chunk(256f), [64..127]=dlat chunk.
    // Lon/lat warps (2,3): slot = 512 floats of one stream.
    __shared__ float4 ring[4][4][128];
    __shared__ unsigned long long sbuf[4][CAP];

    const int row  = blockIdx.x;
    const int warp = threadIdx.x >> 5;
    const int lane = threadIdx.x & 31;
    unsigned long long* buf = sbuf[warp];

    float thr = __int_as_float(0x7f800000);  // +inf until first rebuild
    int cnt = 0;

    constexpr int NIT = 32;   // all warps: 32 iterations

    const bool is_dist = (warp < 2);
    // dist warps: half-row sources; lon/lat warps: full-row single source.
    const float* srcA = is_dist ? (dlon + (size_t)row * S_DIM + warp * 8192)
                                : ((warp == 2 ? dlon : dlat) + (size_t)row * S_DIM);
    const float* srcB = dlat + (size_t)row * S_DIM + warp * 8192;  // dist only

    // Prologue: fill 3 slots (4 CP16 per warp per slot, uniform).
    #pragma unroll
    for (int p = 0; p < 3; ++p) {
        if (is_dist) {
            CP16(saddr(&ring[warp][p][lane]),      srcA + p * 256 + lane * 4);
            CP16(saddr(&ring[warp][p][32 + lane]), srcA + p * 256 + 128 + lane * 4);
            CP16(saddr(&ring[warp][p][64 + lane]), srcB + p * 256 + lane * 4);
            CP16(saddr(&ring[warp][p][96 + lane]), srcB + p * 256 + 128 + lane * 4);
        } else {
            CP16(saddr(&ring[warp][p][lane]),      srcA + p * 512 + lane * 4);
            CP16(saddr(&ring[warp][p][32 + lane]), srcA + p * 512 + 128 + lane * 4);
            CP16(saddr(&ring[warp][p][64 + lane]), srcA + p * 512 + 256 + lane * 4);
            CP16(saddr(&ring[warp][p][96 + lane]), srcA + p * 512 + 384 + lane * 4);
        }
        CPCOMMIT();
    }

    if (is_dist) {
        // ---- euclidean distance, half-row scan on squared values ----
        const unsigned hbase = (unsigned)(warp * 8192);
        #pragma unroll 1
        for (int it = 0; it < NIT; ++it) {
            CPWAIT2();                               // slot `it` resident
            const int s = it & 3;
            float4 a0 = ring[warp][s][lane];
            float4 a1 = ring[warp][s][32 + lane];
            float4 b0 = ring[warp][s][64 + lane];
            float4 b1 = ring[warp][s][96 + lane];
            int nx = it + 3;
            if (nx < NIT) {
                const int w = nx & 3;
                CP16(saddr(&ring[warp][w][lane]),      srcA + nx * 256 + lane * 4);
                CP16(saddr(&ring[warp][w][32 + lane]), srcA + nx * 256 + 128 + lane * 4);
                CP16(saddr(&ring[warp][w][64 + lane]), srcB + nx * 256 + lane * 4);
                CP16(saddr(&ring[warp][w][96 + lane]), srcB + nx * 256 + 128 + lane * 4);
            }
            CPCOMMIT();
            float s0 = fmaf(a0.x, a0.x, b0.x * b0.x);
            float s1 = fmaf(a0.y, a0.y, b0.y * b0.y);
            float s2 = fmaf(a0.z, a0.z, b0.z * b0.z);
            float s3 = fmaf(a0.w, a0.w, b0.w * b0.w);
            float s4 = fmaf(a1.x, a1.x, b1.x * b1.x);
            float s5 = fmaf(a1.y, a1.y, b1.y * b1.y);
            float s6 = fmaf(a1.z, a1.z, b1.z * b1.z);
            float s7 = fmaf(a1.w, a1.w, b1.w * b1.w);
            float mn = fminf(fminf(fminf(s0, s1), fminf(s2, s3)),
                             fminf(fminf(s4, s5), fminf(s6, s7)));
            if (__any_sync(FULLM, mn <= thr)) {      // rare once thr tightens
                unsigned base = hbase + (unsigned)(it * 256) + (unsigned)lane * 4u;
                filt4(s0, s1, s2, s3, base,        buf, cnt, thr, lane);
                filt4(s4, s5, s6, s7, base + 128u, buf, cnt, thr, lane);
            }
        }
        // Re-key survivors with exact IEEE sqrt; per-half top-16.
        __syncwarp();
        for (int p = lane; p < cnt; p += 32) {
            unsigned long long e = buf[p];
            float d = __fsqrt_rn(__uint_as_float((unsigned)(e >> 32)));
            buf[p] = pack_key(d, (unsigned)e);
        }
        __syncwarp();
        select_sorted(buf, cnt, NH, lane);           // buf[0..15] sorted
    } else {
        // ---- |d_lon| (warp 2) / |d_lat| (warp 3), full-row scan ----
        #pragma unroll 1
        for (int it = 0; it < NIT; ++it) {
            CPWAIT2();
            const int s = it & 3;
            float4 a0 = ring[warp][s][lane];
            float4 a1 = ring[warp][s][32 + lane];
            float4 a2 = ring[warp][s][64 + lane];
            float4 a3 = ring[warp][s][96 + lane];
            int nx = it + 3;
            if (nx < NIT) {
                const int w = nx & 3;
                CP16(saddr(&ring[warp][w][lane]),      srcA + nx * 512 + lane * 4);
                CP16(saddr(&ring[warp][w][32 + lane]), srcA + nx * 512 + 128 + lane * 4);
                CP16(saddr(&ring[warp][w][64 + lane]), srcA + nx * 512 + 256 + lane * 4);
                CP16(saddr(&ring[warp][w][96 + lane]), srcA + nx * 512 + 384 + lane * 4);
            }
            CPCOMMIT();
            float m0 = fminf(fminf(fabsf(a0.x), fabsf(a0.y)), fminf(fabsf(a0.z), fabsf(a0.w)));
            float m1 = fminf(fminf(fabsf(a1.x), fabsf(a1.y)), fminf(fabsf(a1.z), fabsf(a1.w)));
            float m2 = fminf(fminf(fabsf(a2.x), fabsf(a2.y)), fminf(fabsf(a2.z), fabsf(a2.w)));
            float m3 = fminf(fminf(fabsf(a3.x), fabsf(a3.y)), fminf(fabsf(a3.z), fabsf(a3.w)));
            float mn = fminf(fminf(m0, m1), fminf(m2, m3));
            if (__any_sync(FULLM, mn <= thr)) {
                unsigned base = (unsigned)(it * 512) + (unsigned)lane * 4u;
                filt4(fabsf(a0.x), fabsf(a0.y), fabsf(a0.z), fabsf(a0.w), base,        buf, cnt, thr, lane);
                filt4(fabsf(a1.x), fabsf(a1.y), fabsf(a1.z), fabsf(a1.w), base + 128u, buf, cnt, thr, lane);
                filt4(fabsf(a2.x), fabsf(a2.y), fabsf(a2.z), fabsf(a2.w), base + 256u, buf, cnt, thr, lane);
                filt4(fabsf(a3.x), fabsf(a3.y), fabsf(a3.z), fabsf(a3.w), base + 384u, buf, cnt, thr, lane);
            }
        }
        __syncwarp();
        select_sorted(buf, cnt, NH, lane);
        const size_t obase = (warp == 2) ? OFF_ILON : OFF_ILAT;
        if (lane < NH) {
            unsigned idx = (unsigned)buf[lane];
            out[obase + (size_t)row * NH + lane] = (float)idx;
        }
    }

    __syncthreads();   // halves' top-16 visible to warp 0

    if (warp == 0) {
        // Merge two sorted 16-lists: top-16 of 32 unique keys, 16 rounds.
        unsigned long long k = (lane < NH) ? sbuf[0][lane] : sbuf[1][lane - NH];
        unsigned long long res = 0;
        #pragma unroll
        for (int r = 0; r < NH; ++r) {
            unsigned long long g = warp_min64(k);
            if (k == g) k = ~0ull;
            if (lane == r) res = g;      // lane r holds r-th smallest
        }
        unsigned idx = (unsigned)res;
        if (lane < NH)
            out[OFF_IDIST + (size_t)row * NH + lane] = (float)idx;
        // x_nearest gather: out[b][row][j] = x[b][idx_j]  (e == 1)
        unsigned idxs = idx;  // lane j (<16) holds idx_j; broadcast via shfl
        #pragma unroll
        for (int p = lane; p < B_DIM * NH; p += 32) {
            int b = p >> 4;
            int j = p & 15;
            unsigned ij = __shfl_sync(FULLM, idxs, j);
            out[OFF_XNEAR + (size_t)b * (T_DIM * NH) + (size_t)row * NH + j] =
                x[(size_t)b * S_DIM + ij];
        }
    }
}

extern "C" void kernel_launch(void* const* d_in, const int* in_sizes, int n_in,
                              void* d_out, int out_size) {
    (void)in_sizes; (void)n_in; (void)out_size;
    const float* x    = (const float*)d_in[0];
    const float* dlon = (const float*)d_in[1];
    const float* dlat = (const float*)d_in[2];
    nn_topk_kernel<<<T_DIM, 128>>>(x, dlon, dlat, (float*)d_out);
}

// round 11
// speedup vs baseline: 1.1780x; 1.1780x over previous
#include <cuda_runtime.h>
#include <stdint.h>

constexpr int S_DIM = 16384;
constexpr int T_DIM = 8192;
constexpr int B_DIM = 16;
constexpr int NH    = 16;
constexpr int KEEP  = 24;
constexpr int CAP   = 128;
constexpr int TRIG  = 96;
constexpr unsigned FULLM = 0xFFFFFFFFu;

constexpr size_t OFF_XNEAR = 0;
constexpr size_t OFF_IDIST = (size_t)B_DIM * T_DIM * NH;      // 2097152
constexpr size_t OFF_ILON  = OFF_IDIST + (size_t)T_DIM * NH;  // 2228224
constexpr size_t OFF_ILAT  = OFF_ILON  + (size_t)T_DIM * NH;  // 2359296

__device__ __forceinline__ unsigned saddr(const void* p) {
    return (unsigned)__cvta_generic_to_shared(p);
}
#define CP16(dst_s, src_g) \
    asm volatile("cp.async.cg.shared.global [%0], [%1], 16;" :: "r"(dst_s), "l"(src_g))
#define CPCOMMIT() asm volatile("cp.async.commit_group;" ::: "memory")
#define CPWAIT6()  asm volatile("cp.async.wait_group 6;"  ::: "memory")

// Pack (nonneg float, index): unsigned order == (value asc, index asc),
// exactly jax.lax.top_k's stable order.
__device__ __forceinline__ unsigned long long pack_key(float v, unsigned idx) {
    return ((unsigned long long)__float_as_uint(v) << 32) | idx;
}

__device__ __forceinline__ unsigned long long warp_min64(unsigned long long v) {
    #pragma unroll
    for (int o = 16; o > 0; o >>= 1) {
        unsigned long long w = __shfl_xor_sync(FULLM, v, o);
        if (w < v) v = w;
    }
    return v;
}

// Warp-collective: write `rounds` smallest keys of buf[0..cnt) sorted into
// buf[0..rounds); returns the rounds-th smallest. Keys unique (distinct idx).
__device__ __forceinline__ unsigned long long select_sorted(
    unsigned long long* buf, int cnt, int rounds, int lane)
{
    unsigned long long k[CAP / 32];
    unsigned long long lmin = ~0ull;
    #pragma unroll
    for (int q = 0; q < CAP / 32; q++) {
        int p = lane + 32 * q;
        k[q] = (p < cnt) ? buf[p] : ~0ull;
        if (k[q] < lmin) lmin = k[q];
    }
    unsigned long long g = ~0ull;
    for (int r = 0; r < rounds; r++) {
        g = warp_min64(lmin);
        if (lmin == g) {
            unsigned long long nl = ~0ull;
            #pragma unroll
            for (int q = 0; q < CAP / 32; q++) {
                if (k[q] == g) k[q] = ~0ull;
                if (k[q] < nl) nl = k[q];
            }
            lmin = nl;
        }
        if (lane == 0) buf[r] = g;
    }
    __syncwarp();
    return g;
}

// Append passing lanes; rebuild keeps KEEP best and tightens thr (inclusive).
__device__ __forceinline__ void try_append(bool p, float v, unsigned idx,
    unsigned long long* buf, int& cnt, float& thr, int lane)
{
    unsigned m = __ballot_sync(FULLM, p);
    if (m == 0) return;
    if (p) buf[cnt + __popc(m & ((1u << lane) - 1u))] = pack_key(v, idx);
    cnt += __popc(m);
    if (cnt > TRIG) {
        __syncwarp();
        unsigned long long g = select_sorted(buf, cnt, KEEP, lane);
        cnt = KEEP;
        thr = __uint_as_float((unsigned)(g >> 32));
    }
}

__device__ __forceinline__ void filt4(float s0, float s1, float s2, float s3,
    unsigned base, unsigned long long* buf, int& cnt, float& thr, int lane)
{
    try_append(s0 <= thr, s0, base + 0u, buf, cnt, thr, lane);
    try_append(s1 <= thr, s1, base + 1u, buf, cnt, thr, lane);
    try_append(s2 <= thr, s2, base + 2u, buf, cnt, thr, lane);
    try_append(s3 <= thr, s3, base + 3u, buf, cnt, thr, lane);
}

struct TS { int cnt; float thr; };

// Rare-path processors: re-read the smem slot, recompute, filter.
// State passed/returned BY VALUE so the caller's cnt/thr stay in registers.
__device__ __noinline__ TS rare_dist(const float4* sa, const float4* sb,
    unsigned base, unsigned long long* buf, int cnt, float thr, int lane)
{
    float4 a = sa[lane], b = sb[lane];
    float s0 = fmaf(a.x, a.x, b.x * b.x);
    float s1 = fmaf(a.y, a.y, b.y * b.y);
    float s2 = fmaf(a.z, a.z, b.z * b.z);
    float s3 = fmaf(a.w, a.w, b.w * b.w);
    filt4(s0, s1, s2, s3, base + (unsigned)lane * 4u, buf, cnt, thr, lane);
    return {cnt, thr};
}

__device__ __noinline__ TS rare_abs(const float4* sa,
    unsigned base, unsigned long long* buf, int cnt, float thr, int lane)
{
    #pragma unroll
    for (int q = 0; q < 2; ++q) {
        float4 a = sa[q * 32 + lane];
        filt4(fabsf(a.x), fabsf(a.y), fabsf(a.z), fabsf(a.w),
              base + (unsigned)(q * 128) + (unsigned)lane * 4u, buf, cnt, thr, lane);
    }
    return {cnt, thr};
}

__global__ __launch_bounds__(128)
void nn_topk_kernel(const float* __restrict__ x,
                    const float* __restrict__ dlon,
                    const float* __restrict__ dlat,
                    float* __restrict__ out)
{
    // 4 warps x 8 slots x 1KB. Dist warps (0,1): slot = 128 dlon elems
    // (float4[0..31]) + 128 dlat elems (float4[32..63]). Abs warps (2,3):
    // slot = 256 contiguous elems of one stream.
    __shared__ float4 ring[4][8][64];
    __shared__ unsigned long long sbuf[4][CAP];

    const int row  = blockIdx.x;
    const int warp = threadIdx.x >> 5;
    const int lane = threadIdx.x & 31;
    unsigned long long* buf = sbuf[warp];

    float thr = __int_as_float(0x7f800000);  // +inf until first rebuild
    int cnt = 0;

    const bool is_dist = (warp < 2);
    const float* pA;
    const float* pB;
    int stride;
    if (is_dist) {         // half-row dist scan
        pA = dlon + (size_t)row * S_DIM + warp * 8192;
        pB = dlat + (size_t)row * S_DIM + warp * 8192;
        stride = 128;
    } else {               // full-row abs scan; "streams" = chunk halves
        pA = (warp == 2 ? dlon : dlat) + (size_t)row * S_DIM;
        pB = pA + 128;
        stride = 256;
    }

    constexpr int NIT = 64;  // every warp: 64 iterations x 1KB

    // Prologue: slots 0..6, one commit group each (2 CP16 per warp, uniform).
    #pragma unroll
    for (int p = 0; p < 7; ++p) {
        CP16(saddr(&ring[warp][p][lane]),      pA + p * stride + lane * 4);
        CP16(saddr(&ring[warp][p][32 + lane]), pB + p * stride + lane * 4);
        CPCOMMIT();
    }
    const float* rA = pA + 7 * stride;   // refill cursors (chunk it+7)
    const float* rB = pB + 7 * stride;

    if (is_dist) {
        unsigned base = (unsigned)(warp * 8192);
        auto iter = [&](int it, bool refill) {
            CPWAIT6();
            const int s = it & 7;
            float4 a = ring[warp][s][lane];
            float4 b = ring[warp][s][32 + lane];
            if (refill) {
                const int w = (it + 7) & 7;
                CP16(saddr(&ring[warp][w][lane]),      rA + lane * 4);
                CP16(saddr(&ring[warp][w][32 + lane]), rB + lane * 4);
                rA += stride; rB += stride;
            }
            CPCOMMIT();
            float s0 = fmaf(a.x, a.x, b.x * b.x);
            float s1 = fmaf(a.y, a.y, b.y * b.y);
            float s2 = fmaf(a.z, a.z, b.z * b.z);
            float s3 = fmaf(a.w, a.w, b.w * b.w);
            float mn = fminf(fminf(s0, s1), fminf(s2, s3));
            if (__any_sync(FULLM, mn <= thr)) {          // rare once thr tightens
                TS t = rare_dist(&ring[warp][s][0], &ring[warp][s][32],
                                 base, buf, cnt, thr, lane);
                cnt = t.cnt; thr = t.thr;
            }
            base += 128;
        };
        #pragma unroll 8
        for (int it = 0; it < 57; ++it) iter(it, true);
        #pragma unroll
        for (int it = 57; it < NIT; ++it) iter(it, false);

        // Re-key survivors with exact IEEE sqrt; per-half top-16 sorted.
        __syncwarp();
        for (int p = lane; p < cnt; p += 32) {
            unsigned long long e = buf[p];
            float d = __fsqrt_rn(__uint_as_float((unsigned)(e >> 32)));
            buf[p] = pack_key(d, (unsigned)e);
        }
        __syncwarp();
        select_sorted(buf, cnt, NH, lane);               // sbuf[warp][0..15]
    } else {
        unsigned base = 0;
        auto iter = [&](int it, bool refill) {
            CPWAIT6();
            const int s = it & 7;
            float4 a0 = ring[warp][s][lane];
            float4 a1 = ring[warp][s][32 + lane];
            if (refill) {
                const int w = (it + 7) & 7;
                CP16(saddr(&ring[warp][w][lane]),      rA + lane * 4);
                CP16(saddr(&ring[warp][w][32 + lane]), rB + lane * 4);
                rA += stride; rB += stride;
            }
            CPCOMMIT();
            float m0 = fminf(fminf(fabsf(a0.x), fabsf(a0.y)),
                             fminf(fabsf(a0.z), fabsf(a0.w)));
            float m1 = fminf(fminf(fabsf(a1.x), fabsf(a1.y)),
                             fminf(fabsf(a1.z), fabsf(a1.w)));
            float mn = fminf(m0, m1);
            if (__any_sync(FULLM, mn <= thr)) {
                TS t = rare_abs(&ring[warp][s][0], base, buf, cnt, thr, lane);
                cnt = t.cnt; thr = t.thr;
            }
            base += 256;
        };
        #pragma unroll 8
        for (int it = 0; it < 57; ++it) iter(it, true);
        #pragma unroll
        for (int it = 57; it < NIT; ++it) iter(it, false);

        __syncwarp();
        select_sorted(buf, cnt, NH, lane);
        const size_t obase = (warp == 2) ? OFF_ILON : OFF_ILAT;
        if (lane < NH) {
            unsigned idx = (unsigned)buf[lane];
            out[obase + (size_t)row * NH + lane] = (float)idx;
        }
    }

    __syncthreads();   // dist halves' top-16 visible to warp 0

    if (warp == 0) {
        // Merge two sorted 16-lists (32 unique keys) -> global top-16.
        unsigned long long k = (lane < NH) ? sbuf[0][lane] : sbuf[1][lane - NH];
        unsigned long long res = 0;
        #pragma unroll
        for (int r = 0; r < NH; ++r) {
            unsigned long long g = warp_min64(k);
            if (k == g) k = ~0ull;
            if (lane == r) res = g;          // lane r holds r-th smallest
        }
        unsigned idx = (unsigned)res;
        if (lane < NH)
            out[OFF_IDIST + (size_t)row * NH + lane] = (float)idx;
        // x_nearest gather: out[b][row][j] = x[b][idx_j]   (e == 1)
        #pragma unroll
        for (int p = lane; p < B_DIM * NH; p += 32) {
            int b = p >> 4;
            int j = p & 15;
            unsigned ij = __shfl_sync(FULLM, idx, j);
            out[OFF_XNEAR + (size_t)b * (T_DIM * NH) + (size_t)row * NH + j] =
                x[(size_t)b * S_DIM + ij];
        }
    }
}

extern "C" void kernel_launch(void* const* d_in, const int* in_sizes, int n_in,
                              void* d_out, int out_size) {
    (void)in_sizes; (void)n_in; (void)out_size;
    const float* x    = (const float*)d_in[0];
    const float* dlon = (const float*)d_in[1];
    const float* dlat = (const float*)d_in[2];
    nn_topk_kernel<<<T_DIM, 128>>>(x, dlon, dlat, (float*)d_out);
}